// round 10
// baseline (speedup 1.0000x reference)
#include <cuda_runtime.h>
#include <cuda_fp16.h>
#include <cstdint>

#define D 300
#define TWO_D 600
#define NLAYERS 5
#define MAXN 200000
#define MAXG 1024
#define BN_EPS 1e-5f

#define NT1 10                 // GEMM1: Nc=600 -> 10 n-tiles of 64
#define NKC1 19                // GEMM1: K=300 -> 19 k-chunks of 16
#define NT2 5                  // GEMM2: Nc=300 -> 5 n-tiles of 64
#define NKC2 38                // GEMM2: K=600
#define BTILE_WORDS 512        // B tile: 16k x 64n f16 = 512 words
#define SMEM_BYTES 155648      // 2 * NKC * BM*8 words * 4B  (same for both configs)

// ---------------- scratch (allocation-free: __device__ globals) ----------------
__device__ float g_h[(size_t)MAXN * D];
__device__ float g_agg[(size_t)MAXN * D];
__device__ float g_t[(size_t)MAXN * TWO_D];
__device__ float g_cnt[(size_t)MAXN * 9];
__device__ float g_gavg[(size_t)MAXG * D];
__device__ uint32_t g_w1hi[(size_t)NLAYERS * NT1 * NKC1 * BTILE_WORDS];
__device__ uint32_t g_w1lo[(size_t)NLAYERS * NT1 * NKC1 * BTILE_WORDS];
__device__ uint32_t g_w2hi[(size_t)NLAYERS * NT2 * NKC2 * BTILE_WORDS];
__device__ uint32_t g_w2lo[(size_t)NLAYERS * NT2 * NKC2 * BTILE_WORDS];

// ---------------- h0 = node_emb0[an] + node_emb1[ct]  (also zeros cnt) ----------------
__global__ void init_h_zero_kernel(const int* __restrict__ an, const int* __restrict__ ct,
                                   const float* __restrict__ e0, const float* __restrict__ e1,
                                   float* __restrict__ h, float* __restrict__ cnt, int N) {
    int idx = blockIdx.x * blockDim.x + threadIdx.x;
    if (idx < N * 9) cnt[idx] = 0.f;
    if (idx >= N * D) return;
    int n = idx / D;
    int d = idx - n * D;
    h[idx] = e0[an[n] * D + d] + e1[ct[n] * D + d];
}

// ---------------- per-dst counts of bond-type / bond-direction ----------------
__global__ void count_kernel(const int* __restrict__ bt, const int* __restrict__ bdt,
                             const int* __restrict__ dst, float* __restrict__ cnt, int E) {
    int e = blockIdx.x * blockDim.x + threadIdx.x;
    if (e >= E) return;
    int d = dst[e];
    atomicAdd(&cnt[d * 9 + bt[e]], 1.f);
    atomicAdd(&cnt[d * 9 + 6 + bdt[e]], 1.f);
}

// ---------------- agg = cnt0 @ e0[l] + cnt1 @ e1[l] ----------------
__global__ void agg_init_kernel(const float* __restrict__ cnt,
                                const float* __restrict__ e0, const float* __restrict__ e1,
                                float* __restrict__ agg, int N) {
    int idx = blockIdx.x * blockDim.x + threadIdx.x;
    if (idx >= N * 75) return;
    int n = idx / 75;
    int c = idx - n * 75;
    float4 s = make_float4(0.f, 0.f, 0.f, 0.f);
#pragma unroll
    for (int b = 0; b < 6; b++) {
        float w = cnt[n * 9 + b];
        if (w != 0.f) {
            float4 v = *(const float4*)(e0 + (size_t)b * D + c * 4);
            s.x += w * v.x; s.y += w * v.y; s.z += w * v.z; s.w += w * v.w;
        }
    }
#pragma unroll
    for (int b = 0; b < 3; b++) {
        float w = cnt[n * 9 + 6 + b];
        if (w != 0.f) {
            float4 v = *(const float4*)(e1 + (size_t)b * D + c * 4);
            s.x += w * v.x; s.y += w * v.y; s.z += w * v.z; s.w += w * v.w;
        }
    }
    *(float4*)(agg + (size_t)n * D + c * 4) = s;
}

// ---------------- scatter: agg[dst] += h[src] via vectorized red ----------------
__global__ void scatter_h_kernel(const float* __restrict__ h,
                                 const int* __restrict__ src, const int* __restrict__ dst,
                                 float* __restrict__ agg, int E) {
    int idx = blockIdx.x * blockDim.x + threadIdx.x;
    if (idx >= E * 75) return;
    int e = idx / 75;
    int c = idx - e * 75;
    float4 hv = *(const float4*)(h + (size_t)src[e] * D + c * 4);
    float* out = agg + (size_t)dst[e] * D + c * 4;
    asm volatile("red.global.add.v4.f32 [%0], {%1,%2,%3,%4};"
                 :: "l"(out), "f"(hv.x), "f"(hv.y), "f"(hv.z), "f"(hv.w) : "memory");
}

// ---------------- weight prep: fragment-major f16 hi/lo split (64-wide tiles, R8 layout) ----------------
__global__ void prep_w_kernel(const float* __restrict__ W,
                              uint32_t* __restrict__ ohi, uint32_t* __restrict__ olo,
                              int K, int Nc, int NKC, int total_words) {
    int w = blockIdx.x * blockDim.x + threadIdx.x;
    if (w >= total_words) return;
    int tile = w >> 9;
    int widx = w & 511;
    int ntile = tile / NKC, kc = tile - ntile * NKC;
    int nt = widx >> 6;
    int rem = widx & 63;
    int lane = rem >> 1, reg = rem & 1;
    int g = lane >> 2, t = lane & 3;
    int n = ntile * 64 + nt * 8 + g;
    int k0 = kc * 16 + reg * 8 + t * 2;
    float v0 = (n < Nc && k0 < K)     ? W[(size_t)k0 * Nc + n]       : 0.f;
    float v1 = (n < Nc && k0 + 1 < K) ? W[(size_t)(k0 + 1) * Nc + n] : 0.f;
    __half h0 = __float2half_rn(v0), h1 = __float2half_rn(v1);
    __half l0 = __float2half_rn(v0 - __half2float(h0));
    __half l1 = __float2half_rn(v1 - __half2float(h1));
    uint32_t ph = (uint32_t)__half_as_ushort(h0) | ((uint32_t)__half_as_ushort(h1) << 16);
    uint32_t pl = (uint32_t)__half_as_ushort(l0) | ((uint32_t)__half_as_ushort(l1) << 16);
    ohi[w] = ph;
    olo[w] = pl;
}

// ---------------- A-block-resident f16 split tensor-core GEMM ----------------
// CTA loads its full BM x K A block into smem once (f16 hi/lo, fragment-major per k-chunk),
// then loops over all N column tiles. Mainloop is sync-free; B fragments LDG'd from the
// pre-split weights (L2-resident) with one-k-chunk prefetch.
// Warp grid WM x WN (8 warps). Warp tile: 32(M) x (64/WN)(N).
template <int MODE, int BM, int WM, int WN>
__global__ __launch_bounds__(256)
void gemm_f16_kernel(const float* __restrict__ A,
                     const uint32_t* __restrict__ Bhi, const uint32_t* __restrict__ Blo,
                     const float* __restrict__ bias,
                     const float* __restrict__ bng, const float* __restrict__ bnb,
                     const float* __restrict__ bnm, const float* __restrict__ bnv,
                     float* __restrict__ C, int M, int K, int Nc, int NKC, int NT) {
    extern __shared__ uint32_t smemw[];
    constexpr int AKC = BM * 8;          // words per k-chunk per (hi|lo) array
    constexpr int NTW = 8 / WN;          // mma n-tiles (8-wide) per warp
    const int tid = threadIdx.x;
    const int lane = tid & 31;
    const int warp = tid >> 5;
    const int wm = warp / WN;
    const int wn = warp % WN;
    const int gg = lane >> 2;
    const int qq = lane & 3;
    const int rowBase = blockIdx.x * BM;
    const int awords = NKC * AKC;
    uint32_t* Ah = smemw;
    uint32_t* Al = smemw + awords;

    // ---- zero A smem (covers M-tail rows and K-pad columns) ----
    for (int i = tid; i < (awords * 2) / 4; i += 256)
        ((uint4*)smemw)[i] = make_uint4(0, 0, 0, 0);
    __syncthreads();

    // ---- load + convert A block once: coalesced float4 stream, split to hi/lo ----
    const int KQ4 = K >> 2;
    for (int idx = tid; idx < BM * KQ4; idx += 256) {
        int row = idx / KQ4, c = idx - row * KQ4;
        int gr = rowBase + row;
        if (gr >= M) continue;
        float4 v = *(const float4*)(A + (size_t)gr * K + c * 4);
        int k = c * 4;
        int kc = k >> 4, kl = k & 15;
        int kh = kl >> 3, q0 = (kl & 7) >> 1;
        int mt = row >> 4, r = row & 15, g = r & 7, rh = r >> 3;
        int wbase = kc * AKC + mt * 128 + rh + 2 * kh;
        __half2 h0 = __floats2half2_rn(v.x, v.y);
        float2 b0 = __half22float2(h0);
        __half2 l0 = __floats2half2_rn(v.x - b0.x, v.y - b0.y);
        __half2 h1 = __floats2half2_rn(v.z, v.w);
        float2 b1 = __half22float2(h1);
        __half2 l1 = __floats2half2_rn(v.z - b1.x, v.w - b1.y);
        Ah[wbase + (g * 4 + q0) * 4]     = *reinterpret_cast<uint32_t*>(&h0);
        Ah[wbase + (g * 4 + q0 + 1) * 4] = *reinterpret_cast<uint32_t*>(&h1);
        Al[wbase + (g * 4 + q0) * 4]     = *reinterpret_cast<uint32_t*>(&l0);
        Al[wbase + (g * 4 + q0 + 1) * 4] = *reinterpret_cast<uint32_t*>(&l1);
    }
    __syncthreads();

    // ---- mainloop over column tiles (sync-free) ----
    for (int nt = 0; nt < NT; nt++) {
        float acc[2][NTW][4];
#pragma unroll
        for (int mt = 0; mt < 2; mt++)
#pragma unroll
            for (int j = 0; j < NTW; j++)
#pragma unroll
                for (int i = 0; i < 4; i++) acc[mt][j][i] = 0.f;

        const uint32_t* tb_hi = Bhi + (size_t)nt * NKC * BTILE_WORDS;
        const uint32_t* tb_lo = Blo + (size_t)nt * NKC * BTILE_WORDS;

        uint32_t cbh[NTW][2], cbl[NTW][2], nbh[NTW][2], nbl[NTW][2];
#pragma unroll
        for (int j = 0; j < NTW; j++) {
            uint2 v = *(const uint2*)(tb_hi + (wn * NTW + j) * 64 + lane * 2);
            cbh[j][0] = v.x; cbh[j][1] = v.y;
            uint2 w2 = *(const uint2*)(tb_lo + (wn * NTW + j) * 64 + lane * 2);
            cbl[j][0] = w2.x; cbl[j][1] = w2.y;
        }

        for (int kc = 0; kc < NKC; kc++) {
            bool has_next = (kc + 1) < NKC;
            if (has_next) {
#pragma unroll
                for (int j = 0; j < NTW; j++) {
                    uint2 v = *(const uint2*)(tb_hi + (kc + 1) * BTILE_WORDS + (wn * NTW + j) * 64 + lane * 2);
                    nbh[j][0] = v.x; nbh[j][1] = v.y;
                    uint2 w2 = *(const uint2*)(tb_lo + (kc + 1) * BTILE_WORDS + (wn * NTW + j) * 64 + lane * 2);
                    nbl[j][0] = w2.x; nbl[j][1] = w2.y;
                }
            }
            uint32_t ah[2][4], al[2][4];
#pragma unroll
            for (int mt = 0; mt < 2; mt++) {
                const uint32_t* ap = Ah + kc * AKC + (wm * 2 + mt) * 128 + lane * 4;
                uint4 x = *(const uint4*)ap;
                ah[mt][0] = x.x; ah[mt][1] = x.y; ah[mt][2] = x.z; ah[mt][3] = x.w;
                const uint32_t* alp = Al + kc * AKC + (wm * 2 + mt) * 128 + lane * 4;
                uint4 y = *(const uint4*)alp;
                al[mt][0] = y.x; al[mt][1] = y.y; al[mt][2] = y.z; al[mt][3] = y.w;
            }
#define MMA(CC, AA, BB) \
    asm volatile("mma.sync.aligned.m16n8k16.row.col.f32.f16.f16.f32 " \
                 "{%0,%1,%2,%3}, {%4,%5,%6,%7}, {%8,%9}, {%0,%1,%2,%3};" \
                 : "+f"(CC[0]), "+f"(CC[1]), "+f"(CC[2]), "+f"(CC[3]) \
                 : "r"(AA[0]), "r"(AA[1]), "r"(AA[2]), "r"(AA[3]), "r"(BB[0]), "r"(BB[1]))
#pragma unroll
            for (int mt = 0; mt < 2; mt++)
#pragma unroll
                for (int j = 0; j < NTW; j++) MMA(acc[mt][j], ah[mt], cbh[j]);
#pragma unroll
            for (int mt = 0; mt < 2; mt++)
#pragma unroll
                for (int j = 0; j < NTW; j++) MMA(acc[mt][j], al[mt], cbh[j]);
#pragma unroll
            for (int mt = 0; mt < 2; mt++)
#pragma unroll
                for (int j = 0; j < NTW; j++) MMA(acc[mt][j], ah[mt], cbl[j]);
#undef MMA
            if (has_next) {
#pragma unroll
                for (int j = 0; j < NTW; j++) {
                    cbh[j][0] = nbh[j][0]; cbh[j][1] = nbh[j][1];
                    cbl[j][0] = nbl[j][0]; cbl[j][1] = nbl[j][1];
                }
            }
        }

        // ---- epilogue for this column tile ----
#pragma unroll
        for (int j = 0; j < NTW; j++) {
            int col = nt * 64 + (wn * NTW + j) * 8 + qq * 2;
            if (col >= Nc) continue;
            float bia0 = bias[col], bia1 = bias[col + 1];
            float sc0 = 1.f, sc1 = 1.f, sh0 = 0.f, sh1 = 0.f;
            if (MODE >= 2) {
                sc0 = bng[col] * rsqrtf(bnv[col] + BN_EPS);
                sc1 = bng[col + 1] * rsqrtf(bnv[col + 1] + BN_EPS);
                sh0 = bnb[col] - bnm[col] * sc0;
                sh1 = bnb[col + 1] - bnm[col + 1] * sc1;
            }
#pragma unroll
            for (int mt = 0; mt < 2; mt++) {
                float* c = acc[mt][j];
#pragma unroll
                for (int half = 0; half < 2; half++) {
                    int r = rowBase + (wm * 2 + mt) * 16 + gg + half * 8;
                    if (r >= M) continue;
                    float v0 = c[half * 2 + 0] + bia0;
                    float v1 = c[half * 2 + 1] + bia1;
                    if (MODE >= 2) { v0 = v0 * sc0 + sh0; v1 = v1 * sc1 + sh1; }
                    if (MODE == 1 || MODE == 3) { v0 = fmaxf(v0, 0.f); v1 = fmaxf(v1, 0.f); }
                    *(float2*)(C + (size_t)r * Nc + col) = make_float2(v0, v1);
                }
            }
        }
    }
}

// ---------------- avg pool per graph ----------------
__device__ __forceinline__ int lower_bound_dev(const int* a, int n, int v) {
    int lo = 0, hi = n;
    while (lo < hi) {
        int m = (lo + hi) >> 1;
        if (a[m] < v) lo = m + 1; else hi = m;
    }
    return lo;
}

__global__ void pool_kernel(const float* __restrict__ h, const int* __restrict__ gid,
                            float* __restrict__ gavg, int N) {
    __shared__ int sh[2];
    int g = blockIdx.x;
    if (threadIdx.x == 0) sh[0] = lower_bound_dev(gid, N, g);
    if (threadIdx.x == 1) sh[1] = lower_bound_dev(gid, N, g + 1);
    __syncthreads();
    int lo = sh[0], hi = sh[1];
    int d = threadIdx.x;
    if (d >= D) return;
    float s = 0.f;
    for (int n = lo; n < hi; n++) s += h[(size_t)n * D + d];
    float cnt = (float)(hi - lo);
    gavg[(size_t)g * D + d] = s / fmaxf(cnt, 1.0f);
}

// ---------------- small fp32 GEMM for the head ----------------
__global__ __launch_bounds__(256)
void head_gemm_kernel(const float* __restrict__ A, const float* __restrict__ B,
                      const float* __restrict__ bias, float* __restrict__ C,
                      int M, int K, int Nc) {
    int row = blockIdx.y * 16 + (threadIdx.x >> 4);
    int col = blockIdx.x * 64 + (threadIdx.x & 15) * 4;
    if (row >= M || col >= Nc) return;
    float s0 = 0.f, s1 = 0.f, s2 = 0.f, s3 = 0.f;
    const float* a = A + (size_t)row * K;
    for (int k = 0; k < K; k++) {
        float av = a[k];
        const float* b = B + (size_t)k * Nc + col;
        s0 += av * b[0]; s1 += av * b[1]; s2 += av * b[2]; s3 += av * b[3];
    }
    float* out = C + (size_t)row * Nc + col;
    out[0] = s0 + bias[col];
    out[1] = s1 + bias[col + 1];
    out[2] = s2 + bias[col + 2];
    out[3] = s3 + bias[col + 3];
}

// ---------------- launch ----------------
extern "C" void kernel_launch(void* const* d_in, const int* in_sizes, int n_in,
                              void* d_out, int out_size) {
    const int* an  = (const int*)d_in[0];
    const int* ct  = (const int*)d_in[1];
    const int* bt  = (const int*)d_in[2];
    const int* bdt = (const int*)d_in[3];
    const int* src = (const int*)d_in[4];
    const int* dst = (const int*)d_in[5];
    const int* gid = (const int*)d_in[6];
    const int N = in_sizes[0];
    const int E = in_sizes[2];

    int p = 7;
    if (n_in > 7 && in_sizes[7] == 1) p = 8;
    const float* node_emb0 = (const float*)d_in[p + 0];
    const float* node_emb1 = (const float*)d_in[p + 1];
    const float* edge_emb0 = (const float*)d_in[p + 2];
    const float* edge_emb1 = (const float*)d_in[p + 3];
    const float* W1  = (const float*)d_in[p + 4];
    const float* b1  = (const float*)d_in[p + 5];
    const float* W2  = (const float*)d_in[p + 6];
    const float* b2  = (const float*)d_in[p + 7];
    const float* bng = (const float*)d_in[p + 8];
    const float* bnb = (const float*)d_in[p + 9];
    const float* bnm = (const float*)d_in[p + 10];
    const float* bnv = (const float*)d_in[p + 11];
    const float* Wd  = (const float*)d_in[p + 12];
    const float* bd  = (const float*)d_in[p + 13];
    const int G = out_size / 256;

    float *h, *agg, *t, *cnt, *gavg;
    uint32_t *w1hi, *w1lo, *w2hi, *w2lo;
    cudaGetSymbolAddress((void**)&h, g_h);
    cudaGetSymbolAddress((void**)&agg, g_agg);
    cudaGetSymbolAddress((void**)&t, g_t);
    cudaGetSymbolAddress((void**)&cnt, g_cnt);
    cudaGetSymbolAddress((void**)&gavg, g_gavg);
    cudaGetSymbolAddress((void**)&w1hi, g_w1hi);
    cudaGetSymbolAddress((void**)&w1lo, g_w1lo);
    cudaGetSymbolAddress((void**)&w2hi, g_w2hi);
    cudaGetSymbolAddress((void**)&w2lo, g_w2lo);

    cudaFuncSetAttribute(gemm_f16_kernel<1, 128, 4, 2>,
                         cudaFuncAttributeMaxDynamicSharedMemorySize, SMEM_BYTES);
    cudaFuncSetAttribute(gemm_f16_kernel<3, 64, 2, 4>,
                         cudaFuncAttributeMaxDynamicSharedMemorySize, SMEM_BYTES);
    cudaFuncSetAttribute(gemm_f16_kernel<2, 64, 2, 4>,
                         cudaFuncAttributeMaxDynamicSharedMemorySize, SMEM_BYTES);

    const int ND = N * D;
    const int words1 = NT1 * NKC1 * BTILE_WORDS;
    const int words2 = NT2 * NKC2 * BTILE_WORDS;
    const int mtiles128 = (N + 127) / 128;
    const int mtiles64 = (N + 63) / 64;

    init_h_zero_kernel<<<(ND + 255) / 256, 256>>>(an, ct, node_emb0, node_emb1, h, cnt, N);
    count_kernel<<<(E + 255) / 256, 256>>>(bt, bdt, dst, cnt, E);

    for (int l = 0; l < NLAYERS; l++) {
        prep_w_kernel<<<(words1 + 255) / 256, 256>>>(
            W1 + (size_t)l * D * TWO_D,
            w1hi + (size_t)l * words1, w1lo + (size_t)l * words1,
            D, TWO_D, NKC1, words1);
        agg_init_kernel<<<(N * 75 + 255) / 256, 256>>>(
            cnt, edge_emb0 + (size_t)l * 6 * D, edge_emb1 + (size_t)l * 3 * D, agg, N);
        scatter_h_kernel<<<(E * 75 + 255) / 256, 256>>>(h, src, dst, agg, E);
        // t = relu(agg @ W1[l] + b1[l])      [N, 600]
        gemm_f16_kernel<1, 128, 4, 2><<<mtiles128, 256, SMEM_BYTES>>>(
            agg, w1hi + (size_t)l * words1, w1lo + (size_t)l * words1,
            b1 + (size_t)l * TWO_D, nullptr, nullptr, nullptr, nullptr,
            t, N, D, TWO_D, NKC1, NT1);
        prep_w_kernel<<<(words2 + 255) / 256, 256>>>(
            W2 + (size_t)l * TWO_D * D,
            w2hi + (size_t)l * words2, w2lo + (size_t)l * words2,
            TWO_D, D, NKC2, words2);
        // h = [relu(]bn(t @ W2[l] + b2[l])[)]   [N, 300]
        if (l < NLAYERS - 1) {
            gemm_f16_kernel<3, 64, 2, 4><<<mtiles64, 256, SMEM_BYTES>>>(
                t, w2hi + (size_t)l * words2, w2lo + (size_t)l * words2,
                b2 + (size_t)l * D, bng + (size_t)l * D, bnb + (size_t)l * D,
                bnm + (size_t)l * D, bnv + (size_t)l * D,
                h, N, TWO_D, D, NKC2, NT2);
        } else {
            gemm_f16_kernel<2, 64, 2, 4><<<mtiles64, 256, SMEM_BYTES>>>(
                t, w2hi + (size_t)l * words2, w2lo + (size_t)l * words2,
                b2 + (size_t)l * D, bng + (size_t)l * D, bnb + (size_t)l * D,
                bnm + (size_t)l * D, bnv + (size_t)l * D,
                h, N, TWO_D, D, NKC2, NT2);
        }
    }

    pool_kernel<<<G, 320>>>(h, gid, gavg, N);
    head_gemm_kernel<<<dim3(256 / 64, (G + 15) / 16), 256>>>(gavg, Wd, bd, (float*)d_out, G, D, 256);
}

// round 11
// speedup vs baseline: 1.4731x; 1.4731x over previous
#include <cuda_runtime.h>
#include <cuda_fp16.h>
#include <cstdint>

#define D 300
#define TWO_D 600
#define NLAYERS 5
#define MAXN 200000
#define MAXG 1024
#define BN_EPS 1e-5f

#define NT1 10
#define NKC1 19
#define NT2 5
#define NKC2 38
#define BTILE_WORDS 512

// ---------------- scratch (allocation-free: __device__ globals) ----------------
__device__ float g_h[(size_t)MAXN * D];
__device__ float g_agg[(size_t)MAXN * D];
__device__ float g_t[(size_t)MAXN * TWO_D];
__device__ float g_cnt[(size_t)MAXN * 9];
__device__ float g_gavg[(size_t)MAXG * D];
__device__ uint32_t g_w1hi[(size_t)NLAYERS * NT1 * NKC1 * BTILE_WORDS];
__device__ uint32_t g_w1lo[(size_t)NLAYERS * NT1 * NKC1 * BTILE_WORDS];
__device__ uint32_t g_w2hi[(size_t)NLAYERS * NT2 * NKC2 * BTILE_WORDS];
__device__ uint32_t g_w2lo[(size_t)NLAYERS * NT2 * NKC2 * BTILE_WORDS];

// ---------------- h0 = node_emb0[an] + node_emb1[ct]  (also zeros cnt) ----------------
__global__ void init_h_zero_kernel(const int* __restrict__ an, const int* __restrict__ ct,
                                   const float* __restrict__ e0, const float* __restrict__ e1,
                                   float* __restrict__ h, float* __restrict__ cnt, int N) {
    int idx = blockIdx.x * blockDim.x + threadIdx.x;
    if (idx < N * 9) cnt[idx] = 0.f;
    if (idx >= N * D) return;
    int n = idx / D;
    int d = idx - n * D;
    h[idx] = e0[an[n] * D + d] + e1[ct[n] * D + d];
}

// ---------------- per-dst counts of bond-type / bond-direction ----------------
__global__ void count_kernel(const int* __restrict__ bt, const int* __restrict__ bdt,
                             const int* __restrict__ dst, float* __restrict__ cnt, int E) {
    int e = blockIdx.x * blockDim.x + threadIdx.x;
    if (e >= E) return;
    int d = dst[e];
    atomicAdd(&cnt[d * 9 + bt[e]], 1.f);
    atomicAdd(&cnt[d * 9 + 6 + bdt[e]], 1.f);
}

// ---------------- agg = cnt0 @ e0[l] + cnt1 @ e1[l] ----------------
__global__ void agg_init_kernel(const float* __restrict__ cnt,
                                const float* __restrict__ e0, const float* __restrict__ e1,
                                float* __restrict__ agg, int N) {
    int idx = blockIdx.x * blockDim.x + threadIdx.x;
    if (idx >= N * 75) return;
    int n = idx / 75;
    int c = idx - n * 75;
    float4 s = make_float4(0.f, 0.f, 0.f, 0.f);
#pragma unroll
    for (int b = 0; b < 6; b++) {
        float w = cnt[n * 9 + b];
        if (w != 0.f) {
            float4 v = *(const float4*)(e0 + (size_t)b * D + c * 4);
            s.x += w * v.x; s.y += w * v.y; s.z += w * v.z; s.w += w * v.w;
        }
    }
#pragma unroll
    for (int b = 0; b < 3; b++) {
        float w = cnt[n * 9 + 6 + b];
        if (w != 0.f) {
            float4 v = *(const float4*)(e1 + (size_t)b * D + c * 4);
            s.x += w * v.x; s.y += w * v.y; s.z += w * v.z; s.w += w * v.w;
        }
    }
    *(float4*)(agg + (size_t)n * D + c * 4) = s;
}

// ---------------- scatter: agg[dst] += h[src] via vectorized red ----------------
__global__ void scatter_h_kernel(const float* __restrict__ h,
                                 const int* __restrict__ src, const int* __restrict__ dst,
                                 float* __restrict__ agg, int E) {
    int idx = blockIdx.x * blockDim.x + threadIdx.x;
    if (idx >= E * 75) return;
    int e = idx / 75;
    int c = idx - e * 75;
    float4 hv = *(const float4*)(h + (size_t)src[e] * D + c * 4);
    float* out = agg + (size_t)dst[e] * D + c * 4;
    asm volatile("red.global.add.v4.f32 [%0], {%1,%2,%3,%4};"
                 :: "l"(out), "f"(hv.x), "f"(hv.y), "f"(hv.z), "f"(hv.w) : "memory");
}

// ---------------- weight prep: fragment-major f16 hi/lo split ----------------
__global__ void prep_w_kernel(const float* __restrict__ W,
                              uint32_t* __restrict__ ohi, uint32_t* __restrict__ olo,
                              int K, int Nc, int NKC, int total_words) {
    int w = blockIdx.x * blockDim.x + threadIdx.x;
    if (w >= total_words) return;
    int tile = w >> 9;
    int widx = w & 511;
    int ntile = tile / NKC, kc = tile - ntile * NKC;
    int nt = widx >> 6;
    int rem = widx & 63;
    int lane = rem >> 1, reg = rem & 1;
    int g = lane >> 2, t = lane & 3;
    int n = ntile * 64 + nt * 8 + g;
    int k0 = kc * 16 + reg * 8 + t * 2;
    float v0 = (n < Nc && k0 < K)     ? W[(size_t)k0 * Nc + n]       : 0.f;
    float v1 = (n < Nc && k0 + 1 < K) ? W[(size_t)(k0 + 1) * Nc + n] : 0.f;
    __half h0 = __float2half_rn(v0), h1 = __float2half_rn(v1);
    __half l0 = __float2half_rn(v0 - __half2float(h0));
    __half l1 = __float2half_rn(v1 - __half2float(h1));
    uint32_t ph = (uint32_t)__half_as_ushort(h0) | ((uint32_t)__half_as_ushort(h1) << 16);
    uint32_t pl = (uint32_t)__half_as_ushort(l0) | ((uint32_t)__half_as_ushort(l1) << 16);
    ohi[w] = ph;
    olo[w] = pl;
}

// ---------------- f16 split tensor-core GEMM (R8 structure + f16-accum lo terms) ----------------
template <int MODE>
__global__ __launch_bounds__(256, 2)
void gemm_f16_kernel(const float* __restrict__ A,
                     const uint32_t* __restrict__ Bhi, const uint32_t* __restrict__ Blo,
                     const float* __restrict__ bias,
                     const float* __restrict__ bng, const float* __restrict__ bnb,
                     const float* __restrict__ bnm, const float* __restrict__ bnv,
                     float* __restrict__ C, int M, int K, int Nc, int NKC) {
    __shared__ float As[2][2048];
    __shared__ uint32_t Bh[2][512];
    __shared__ uint32_t Bl[2][512];

    const int tid = threadIdx.x;
    const int lane = tid & 31;
    const int warp = tid >> 5;
    const int wm = warp >> 1;
    const int wn = warp & 1;
    const int gg = lane >> 2;
    const int qq = lane & 3;
    const int rowBase = blockIdx.y * 128;
    const int colBase = blockIdx.x * 64;

    // A loader: 2 float4 chunks per thread
    int a_row[2], a_kc[2], a_soff[2];
#pragma unroll
    for (int i = 0; i < 2; i++) {
        int id = tid + i * 256;
        a_row[i] = id >> 2;              // 0..127
        a_kc[i] = (id & 3) * 4;          // 0,4,8,12
        int mt = a_row[i] >> 4;
        int rr = a_row[i] & 15;
        int r7 = rr & 7, rh = rr >> 3;
        int q0 = (a_kc[i] & 7) >> 1;     // 0 or 2
        a_soff[i] = mt * 256 + ((a_kc[i] & 8) ? 128 : 0) + (r7 * 4 + q0) * 4 + 2 * rh;
    }
    const int b_sel = tid >> 7;
    const int b_idx = tid & 127;
    const uint32_t* bthi = Bhi + (size_t)blockIdx.x * NKC * BTILE_WORDS;
    const uint32_t* btlo = Blo + (size_t)blockIdx.x * NKC * BTILE_WORDS;

    float acc[2][4][4];
    uint32_t accl[2][4][2];              // f16x2 accumulators for lo terms
#pragma unroll
    for (int mt = 0; mt < 2; mt++)
#pragma unroll
        for (int nt = 0; nt < 4; nt++) {
#pragma unroll
            for (int i = 0; i < 4; i++) acc[mt][nt][i] = 0.f;
            accl[mt][nt][0] = 0u; accl[mt][nt][1] = 0u;
        }

    float4 av[2];
    uint4 bv;

    auto ldg_tile = [&](int k0) {
#pragma unroll
        for (int i = 0; i < 2; i++) {
            av[i] = make_float4(0.f, 0.f, 0.f, 0.f);
            int gr = rowBase + a_row[i];
            if (gr < M && k0 + a_kc[i] < K)
                av[i] = *(const float4*)(A + (size_t)gr * K + k0 + a_kc[i]);
        }
        int kc = k0 >> 4;
        const uint4* sp = (const uint4*)((b_sel ? btlo : bthi) + (size_t)kc * BTILE_WORDS);
        bv = sp[b_idx];
    };

    auto sts_tile = [&](int s) {
#pragma unroll
        for (int i = 0; i < 2; i++) {
            float* b = &As[s][a_soff[i]];
            *(float2*)b = make_float2(av[i].x, av[i].y);
            *(float2*)(b + 4) = make_float2(av[i].z, av[i].w);
        }
        uint4* dp = (uint4*)(b_sel ? Bl[s] : Bh[s]);
        dp[b_idx] = bv;
    };

    ldg_tile(0);
    sts_tile(0);
    __syncthreads();
    int stage = 0;

    for (int k0 = 0; k0 < K; k0 += 16) {
        bool has_next = (k0 + 16) < K;
        if (has_next) ldg_tile(k0 + 16);

        uint32_t ah[2][4], al[2][4];
#pragma unroll
        for (int mt = 0; mt < 2; mt++) {
            const float* ap = &As[stage][(wm * 2 + mt) * 256 + lane * 4];
            float4 x = *(const float4*)ap;
            float4 y = *(const float4*)(ap + 128);
            float f[8] = {x.x, x.y, x.z, x.w, y.x, y.y, y.z, y.w};
#pragma unroll
            for (int r = 0; r < 4; r++) {
                __half2 hh = __floats2half2_rn(f[2 * r], f[2 * r + 1]);
                ah[mt][r] = *reinterpret_cast<uint32_t*>(&hh);
                float2 bk = __half22float2(hh);
                __half2 ll = __floats2half2_rn(f[2 * r] - bk.x, f[2 * r + 1] - bk.y);
                al[mt][r] = *reinterpret_cast<uint32_t*>(&ll);
            }
        }
        uint32_t bh[4][2], bl[4][2];
#pragma unroll
        for (int nt = 0; nt < 4; nt++) {
            uint2 v = *(const uint2*)(&Bh[stage][(wn * 4 + nt) * 64 + lane * 2]);
            bh[nt][0] = v.x; bh[nt][1] = v.y;
            uint2 w2 = *(const uint2*)(&Bl[stage][(wn * 4 + nt) * 64 + lane * 2]);
            bl[nt][0] = w2.x; bl[nt][1] = w2.y;
        }
#define MMA(CC, AA, BB) \
    asm volatile("mma.sync.aligned.m16n8k16.row.col.f32.f16.f16.f32 " \
                 "{%0,%1,%2,%3}, {%4,%5,%6,%7}, {%8,%9}, {%0,%1,%2,%3};" \
                 : "+f"(CC[0]), "+f"(CC[1]), "+f"(CC[2]), "+f"(CC[3]) \
                 : "r"(AA[0]), "r"(AA[1]), "r"(AA[2]), "r"(AA[3]), "r"(BB[0]), "r"(BB[1]))
#define MMALO(CC, AA, BB) \
    asm volatile("mma.sync.aligned.m16n8k16.row.col.f16.f16.f16.f16 " \
                 "{%0,%1}, {%2,%3,%4,%5}, {%6,%7}, {%0,%1};" \
                 : "+r"(CC[0]), "+r"(CC[1]) \
                 : "r"(AA[0]), "r"(AA[1]), "r"(AA[2]), "r"(AA[3]), "r"(BB[0]), "r"(BB[1]))
#pragma unroll
        for (int mt = 0; mt < 2; mt++)
#pragma unroll
            for (int nt = 0; nt < 4; nt++) MMA(acc[mt][nt], ah[mt], bh[nt]);
#pragma unroll
        for (int mt = 0; mt < 2; mt++)
#pragma unroll
            for (int nt = 0; nt < 4; nt++) MMALO(accl[mt][nt], al[mt], bh[nt]);
#pragma unroll
        for (int mt = 0; mt < 2; mt++)
#pragma unroll
            for (int nt = 0; nt < 4; nt++) MMALO(accl[mt][nt], ah[mt], bl[nt]);
#undef MMA
#undef MMALO

        if (has_next) {
            sts_tile(stage ^ 1);
            __syncthreads();
            stage ^= 1;
        }
    }

    // ---- merge f16 lo accumulators into f32 ----
#pragma unroll
    for (int mt = 0; mt < 2; mt++)
#pragma unroll
        for (int nt = 0; nt < 4; nt++) {
            __half2 l0 = *reinterpret_cast<__half2*>(&accl[mt][nt][0]);
            __half2 l1 = *reinterpret_cast<__half2*>(&accl[mt][nt][1]);
            float2 f0 = __half22float2(l0);
            float2 f1 = __half22float2(l1);
            acc[mt][nt][0] += f0.x;
            acc[mt][nt][1] += f0.y;
            acc[mt][nt][2] += f1.x;
            acc[mt][nt][3] += f1.y;
        }

    // ---- epilogue ----
#pragma unroll
    for (int nt = 0; nt < 4; nt++) {
        int col = colBase + wn * 32 + nt * 8 + qq * 2;
        if (col >= Nc) continue;
        float bia0 = bias[col], bia1 = bias[col + 1];
        float sc0 = 1.f, sc1 = 1.f, sh0 = 0.f, sh1 = 0.f;
        if (MODE >= 2) {
            sc0 = bng[col] * rsqrtf(bnv[col] + BN_EPS);
            sc1 = bng[col + 1] * rsqrtf(bnv[col + 1] + BN_EPS);
            sh0 = bnb[col] - bnm[col] * sc0;
            sh1 = bnb[col + 1] - bnm[col + 1] * sc1;
        }
#pragma unroll
        for (int mt = 0; mt < 2; mt++) {
            float* c = acc[mt][nt];
#pragma unroll
            for (int half = 0; half < 2; half++) {
                int r = rowBase + wm * 32 + mt * 16 + gg + half * 8;
                if (r >= M) continue;
                float v0 = c[half * 2 + 0] + bia0;
                float v1 = c[half * 2 + 1] + bia1;
                if (MODE >= 2) { v0 = v0 * sc0 + sh0; v1 = v1 * sc1 + sh1; }
                if (MODE == 1 || MODE == 3) { v0 = fmaxf(v0, 0.f); v1 = fmaxf(v1, 0.f); }
                *(float2*)(C + (size_t)r * Nc + col) = make_float2(v0, v1);
            }
        }
    }
}

// ---------------- avg pool per graph ----------------
__device__ __forceinline__ int lower_bound_dev(const int* a, int n, int v) {
    int lo = 0, hi = n;
    while (lo < hi) {
        int m = (lo + hi) >> 1;
        if (a[m] < v) lo = m + 1; else hi = m;
    }
    return lo;
}

__global__ void pool_kernel(const float* __restrict__ h, const int* __restrict__ gid,
                            float* __restrict__ gavg, int N) {
    __shared__ int sh[2];
    int g = blockIdx.x;
    if (threadIdx.x == 0) sh[0] = lower_bound_dev(gid, N, g);
    if (threadIdx.x == 1) sh[1] = lower_bound_dev(gid, N, g + 1);
    __syncthreads();
    int lo = sh[0], hi = sh[1];
    int d = threadIdx.x;
    if (d >= D) return;
    float s = 0.f;
    for (int n = lo; n < hi; n++) s += h[(size_t)n * D + d];
    float cnt = (float)(hi - lo);
    gavg[(size_t)g * D + d] = s / fmaxf(cnt, 1.0f);
}

// ---------------- small fp32 GEMM for the head ----------------
__global__ __launch_bounds__(256)
void head_gemm_kernel(const float* __restrict__ A, const float* __restrict__ B,
                      const float* __restrict__ bias, float* __restrict__ C,
                      int M, int K, int Nc) {
    int row = blockIdx.y * 16 + (threadIdx.x >> 4);
    int col = blockIdx.x * 64 + (threadIdx.x & 15) * 4;
    if (row >= M || col >= Nc) return;
    float s0 = 0.f, s1 = 0.f, s2 = 0.f, s3 = 0.f;
    const float* a = A + (size_t)row * K;
    for (int k = 0; k < K; k++) {
        float av = a[k];
        const float* b = B + (size_t)k * Nc + col;
        s0 += av * b[0]; s1 += av * b[1]; s2 += av * b[2]; s3 += av * b[3];
    }
    float* out = C + (size_t)row * Nc + col;
    out[0] = s0 + bias[col];
    out[1] = s1 + bias[col + 1];
    out[2] = s2 + bias[col + 2];
    out[3] = s3 + bias[col + 3];
}

// ---------------- launch ----------------
extern "C" void kernel_launch(void* const* d_in, const int* in_sizes, int n_in,
                              void* d_out, int out_size) {
    const int* an  = (const int*)d_in[0];
    const int* ct  = (const int*)d_in[1];
    const int* bt  = (const int*)d_in[2];
    const int* bdt = (const int*)d_in[3];
    const int* src = (const int*)d_in[4];
    const int* dst = (const int*)d_in[5];
    const int* gid = (const int*)d_in[6];
    const int N = in_sizes[0];
    const int E = in_sizes[2];

    int p = 7;
    if (n_in > 7 && in_sizes[7] == 1) p = 8;
    const float* node_emb0 = (const float*)d_in[p + 0];
    const float* node_emb1 = (const float*)d_in[p + 1];
    const float* edge_emb0 = (const float*)d_in[p + 2];
    const float* edge_emb1 = (const float*)d_in[p + 3];
    const float* W1  = (const float*)d_in[p + 4];
    const float* b1  = (const float*)d_in[p + 5];
    const float* W2  = (const float*)d_in[p + 6];
    const float* b2  = (const float*)d_in[p + 7];
    const float* bng = (const float*)d_in[p + 8];
    const float* bnb = (const float*)d_in[p + 9];
    const float* bnm = (const float*)d_in[p + 10];
    const float* bnv = (const float*)d_in[p + 11];
    const float* Wd  = (const float*)d_in[p + 12];
    const float* bd  = (const float*)d_in[p + 13];
    const int G = out_size / 256;

    float *h, *agg, *t, *cnt, *gavg;
    uint32_t *w1hi, *w1lo, *w2hi, *w2lo;
    cudaGetSymbolAddress((void**)&h, g_h);
    cudaGetSymbolAddress((void**)&agg, g_agg);
    cudaGetSymbolAddress((void**)&t, g_t);
    cudaGetSymbolAddress((void**)&cnt, g_cnt);
    cudaGetSymbolAddress((void**)&gavg, g_gavg);
    cudaGetSymbolAddress((void**)&w1hi, g_w1hi);
    cudaGetSymbolAddress((void**)&w1lo, g_w1lo);
    cudaGetSymbolAddress((void**)&w2hi, g_w2hi);
    cudaGetSymbolAddress((void**)&w2lo, g_w2lo);

    const int ND = N * D;
    const int words1 = NT1 * NKC1 * BTILE_WORDS;
    const int words2 = NT2 * NKC2 * BTILE_WORDS;
    const int mtiles = (N + 127) / 128;

    init_h_zero_kernel<<<(ND + 255) / 256, 256>>>(an, ct, node_emb0, node_emb1, h, cnt, N);
    count_kernel<<<(E + 255) / 256, 256>>>(bt, bdt, dst, cnt, E);

    for (int l = 0; l < NLAYERS; l++) {
        prep_w_kernel<<<(words1 + 255) / 256, 256>>>(
            W1 + (size_t)l * D * TWO_D,
            w1hi + (size_t)l * words1, w1lo + (size_t)l * words1,
            D, TWO_D, NKC1, words1);
        agg_init_kernel<<<(N * 75 + 255) / 256, 256>>>(
            cnt, edge_emb0 + (size_t)l * 6 * D, edge_emb1 + (size_t)l * 3 * D, agg, N);
        scatter_h_kernel<<<(E * 75 + 255) / 256, 256>>>(h, src, dst, agg, E);
        gemm_f16_kernel<1><<<dim3(NT1, mtiles), 256>>>(
            agg, w1hi + (size_t)l * words1, w1lo + (size_t)l * words1,
            b1 + (size_t)l * TWO_D, nullptr, nullptr, nullptr, nullptr,
            t, N, D, TWO_D, NKC1);
        prep_w_kernel<<<(words2 + 255) / 256, 256>>>(
            W2 + (size_t)l * TWO_D * D,
            w2hi + (size_t)l * words2, w2lo + (size_t)l * words2,
            TWO_D, D, NKC2, words2);
        if (l < NLAYERS - 1) {
            gemm_f16_kernel<3><<<dim3(NT2, mtiles), 256>>>(
                t, w2hi + (size_t)l * words2, w2lo + (size_t)l * words2,
                b2 + (size_t)l * D, bng + (size_t)l * D, bnb + (size_t)l * D,
                bnm + (size_t)l * D, bnv + (size_t)l * D,
                h, N, TWO_D, D, NKC2);
        } else {
            gemm_f16_kernel<2><<<dim3(NT2, mtiles), 256>>>(
                t, w2hi + (size_t)l * words2, w2lo + (size_t)l * words2,
                b2 + (size_t)l * D, bng + (size_t)l * D, bnb + (size_t)l * D,
                bnm + (size_t)l * D, bnv + (size_t)l * D,
                h, N, TWO_D, D, NKC2);
        }
    }

    pool_kernel<<<G, 320>>>(h, gid, gavg, N);
    head_gemm_kernel<<<dim3(256 / 64, (G + 15) / 16), 256>>>(gavg, Wd, bd, (float*)d_out, G, D, 256);
}

// round 13
// speedup vs baseline: 1.5323x; 1.0402x over previous
#include <cuda_runtime.h>
#include <cuda_fp16.h>
#include <cstdint>

#define D 300
#define TWO_D 600
#define NLAYERS 5
#define MAXN 200000
#define MAXE 400000
#define MAXG 1024
#define BN_EPS 1e-5f

#define NT1 10
#define NKC1 19
#define NT2 5
#define NKC2 38
#define BTILE_WORDS 512

// ---------------- scratch (allocation-free: __device__ globals) ----------------
__device__ float g_h[(size_t)MAXN * D];
__device__ float g_agg[(size_t)MAXN * D];
__device__ float g_t[(size_t)MAXN * TWO_D];
__device__ float g_cnt[(size_t)MAXN * 9];
__device__ float g_gavg[(size_t)MAXG * D];
__device__ int g_deg[MAXN + 1];
__device__ int g_offs[MAXN + 1];
__device__ int g_bsum[256];
__device__ int g_cursor[MAXN];
__device__ int g_ssrc[MAXE];
__device__ uint32_t g_w1hi[(size_t)NLAYERS * NT1 * NKC1 * BTILE_WORDS];
__device__ uint32_t g_w1lo[(size_t)NLAYERS * NT1 * NKC1 * BTILE_WORDS];
__device__ uint32_t g_w2hi[(size_t)NLAYERS * NT2 * NKC2 * BTILE_WORDS];
__device__ uint32_t g_w2lo[(size_t)NLAYERS * NT2 * NKC2 * BTILE_WORDS];

// ---------------- h0 = node_emb0[an] + node_emb1[ct]  (also zeros cnt, deg) ----------------
__global__ void init_h_zero_kernel(const int* __restrict__ an, const int* __restrict__ ct,
                                   const float* __restrict__ e0, const float* __restrict__ e1,
                                   float* __restrict__ h, float* __restrict__ cnt,
                                   int* __restrict__ deg, int N) {
    int idx = blockIdx.x * blockDim.x + threadIdx.x;
    if (idx < N * 9) cnt[idx] = 0.f;
    if (idx <= N) deg[idx] = 0;
    if (idx >= N * D) return;
    int n = idx / D;
    int d = idx - n * D;
    h[idx] = e0[an[n] * D + d] + e1[ct[n] * D + d];
}

// ---------------- per-dst counts of bond-type / bond-direction + degree ----------------
__global__ void count_kernel(const int* __restrict__ bt, const int* __restrict__ bdt,
                             const int* __restrict__ dst, float* __restrict__ cnt,
                             int* __restrict__ deg, int E) {
    int e = blockIdx.x * blockDim.x + threadIdx.x;
    if (e >= E) return;
    int d = dst[e];
    atomicAdd(&cnt[d * 9 + bt[e]], 1.f);
    atomicAdd(&cnt[d * 9 + 6 + bdt[e]], 1.f);
    atomicAdd(&deg[d], 1);
}

// ---------------- prefix scan (3-phase) over deg[0..n) -> offs (exclusive) ----------------
__global__ void scan_block_kernel(const int* __restrict__ deg, int* __restrict__ offs,
                                  int* __restrict__ bsum, int n) {
    __shared__ int sm[1024];
    int gid = blockIdx.x * 1024 + threadIdx.x;
    int v = (gid < n) ? deg[gid] : 0;
    sm[threadIdx.x] = v;
    __syncthreads();
    for (int off = 1; off < 1024; off <<= 1) {
        int t = (threadIdx.x >= off) ? sm[threadIdx.x - off] : 0;
        __syncthreads();
        sm[threadIdx.x] += t;
        __syncthreads();
    }
    if (gid < n) offs[gid] = sm[threadIdx.x] - v;  // exclusive
    if (threadIdx.x == 1023) bsum[blockIdx.x] = sm[1023];
}

__global__ void scan_sums_kernel(int* __restrict__ bsum, int nb) {
    __shared__ int sm[256];
    int v = (threadIdx.x < nb) ? bsum[threadIdx.x] : 0;
    sm[threadIdx.x] = v;
    __syncthreads();
    for (int off = 1; off < 256; off <<= 1) {
        int t = (threadIdx.x >= off) ? sm[threadIdx.x - off] : 0;
        __syncthreads();
        sm[threadIdx.x] += t;
        __syncthreads();
    }
    if (threadIdx.x < nb) bsum[threadIdx.x] = sm[threadIdx.x] - v;  // exclusive
}

__global__ void scan_add_kernel(int* __restrict__ offs, const int* __restrict__ bsum,
                                int* __restrict__ cursor, int n, int N) {
    int gid = blockIdx.x * 1024 + threadIdx.x;
    if (gid >= n) return;
    int o = offs[gid] + bsum[blockIdx.x];
    offs[gid] = o;
    if (gid < N) cursor[gid] = o;
}

// ---------------- fill CSR: sorted_src bucketed by dst ----------------
__global__ void fill_kernel(const int* __restrict__ src, const int* __restrict__ dst,
                            int* __restrict__ cursor, int* __restrict__ ssrc, int E) {
    int e = blockIdx.x * blockDim.x + threadIdx.x;
    if (e >= E) return;
    int p = atomicAdd(&cursor[dst[e]], 1);
    ssrc[p] = src[e];
}

// ---------------- fused gather: agg[n] = sum_{e->n} h[src_e] + cnt-weighted edge embs ----------------
__global__ void gather_agg_kernel(const float* __restrict__ h,
                                  const int* __restrict__ offs, const int* __restrict__ ssrc,
                                  const float* __restrict__ cnt,
                                  const float* __restrict__ e0, const float* __restrict__ e1,
                                  float* __restrict__ agg, int N) {
    int idx = blockIdx.x * blockDim.x + threadIdx.x;
    if (idx >= N * 75) return;
    int n = idx / 75;
    int c = idx - n * 75;
    float4 s = make_float4(0.f, 0.f, 0.f, 0.f);
#pragma unroll
    for (int b = 0; b < 6; b++) {
        float w = cnt[n * 9 + b];
        if (w != 0.f) {
            float4 v = *(const float4*)(e0 + (size_t)b * D + c * 4);
            s.x += w * v.x; s.y += w * v.y; s.z += w * v.z; s.w += w * v.w;
        }
    }
#pragma unroll
    for (int b = 0; b < 3; b++) {
        float w = cnt[n * 9 + 6 + b];
        if (w != 0.f) {
            float4 v = *(const float4*)(e1 + (size_t)b * D + c * 4);
            s.x += w * v.x; s.y += w * v.y; s.z += w * v.z; s.w += w * v.w;
        }
    }
    int start = offs[n], end = offs[n + 1];
    for (int j = start; j < end; j++) {
        float4 v = *(const float4*)(h + (size_t)ssrc[j] * D + c * 4);
        s.x += v.x; s.y += v.y; s.z += v.z; s.w += v.w;
    }
    *(float4*)(agg + (size_t)n * D + c * 4) = s;
}

// ---------------- weight prep: fragment-major f16 hi/lo split ----------------
__global__ void prep_w_kernel(const float* __restrict__ W,
                              uint32_t* __restrict__ ohi, uint32_t* __restrict__ olo,
                              int K, int Nc, int NKC, int total_words) {
    int w = blockIdx.x * blockDim.x + threadIdx.x;
    if (w >= total_words) return;
    int tile = w >> 9;
    int widx = w & 511;
    int ntile = tile / NKC, kc = tile - ntile * NKC;
    int nt = widx >> 6;
    int rem = widx & 63;
    int lane = rem >> 1, reg = rem & 1;
    int g = lane >> 2, t = lane & 3;
    int n = ntile * 64 + nt * 8 + g;
    int k0 = kc * 16 + reg * 8 + t * 2;
    float v0 = (n < Nc && k0 < K)     ? W[(size_t)k0 * Nc + n]       : 0.f;
    float v1 = (n < Nc && k0 + 1 < K) ? W[(size_t)(k0 + 1) * Nc + n] : 0.f;
    __half h0 = __float2half_rn(v0), h1 = __float2half_rn(v1);
    __half l0 = __float2half_rn(v0 - __half2float(h0));
    __half l1 = __float2half_rn(v1 - __half2float(h1));
    uint32_t ph = (uint32_t)__half_as_ushort(h0) | ((uint32_t)__half_as_ushort(h1) << 16);
    uint32_t pl = (uint32_t)__half_as_ushort(l0) | ((uint32_t)__half_as_ushort(l1) << 16);
    ohi[w] = ph;
    olo[w] = pl;
}

// ---------------- f16 split tensor-core GEMM (f16-accum lo terms) ----------------
template <int MODE>
__global__ __launch_bounds__(256, 2)
void gemm_f16_kernel(const float* __restrict__ A,
                     const uint32_t* __restrict__ Bhi, const uint32_t* __restrict__ Blo,
                     const float* __restrict__ bias,
                     const float* __restrict__ bng, const float* __restrict__ bnb,
                     const float* __restrict__ bnm, const float* __restrict__ bnv,
                     float* __restrict__ C, int M, int K, int Nc, int NKC) {
    __shared__ float As[2][2048];
    __shared__ uint32_t Bh[2][512];
    __shared__ uint32_t Bl[2][512];

    const int tid = threadIdx.x;
    const int lane = tid & 31;
    const int warp = tid >> 5;
    const int wm = warp >> 1;
    const int wn = warp & 1;
    const int gg = lane >> 2;
    const int qq = lane & 3;
    const int rowBase = blockIdx.y * 128;
    const int colBase = blockIdx.x * 64;

    int a_row[2], a_kc[2], a_soff[2];
#pragma unroll
    for (int i = 0; i < 2; i++) {
        int id = tid + i * 256;
        a_row[i] = id >> 2;
        a_kc[i] = (id & 3) * 4;
        int mt = a_row[i] >> 4;
        int rr = a_row[i] & 15;
        int r7 = rr & 7, rh = rr >> 3;
        int q0 = (a_kc[i] & 7) >> 1;
        a_soff[i] = mt * 256 + ((a_kc[i] & 8) ? 128 : 0) + (r7 * 4 + q0) * 4 + 2 * rh;
    }
    const int b_sel = tid >> 7;
    const int b_idx = tid & 127;
    const uint32_t* bthi = Bhi + (size_t)blockIdx.x * NKC * BTILE_WORDS;
    const uint32_t* btlo = Blo + (size_t)blockIdx.x * NKC * BTILE_WORDS;

    float acc[2][4][4];
    uint32_t accl[2][4][2];
#pragma unroll
    for (int mt = 0; mt < 2; mt++)
#pragma unroll
        for (int nt = 0; nt < 4; nt++) {
#pragma unroll
            for (int i = 0; i < 4; i++) acc[mt][nt][i] = 0.f;
            accl[mt][nt][0] = 0u; accl[mt][nt][1] = 0u;
        }

    float4 av[2];
    uint4 bv;

    auto ldg_tile = [&](int k0) {
#pragma unroll
        for (int i = 0; i < 2; i++) {
            av[i] = make_float4(0.f, 0.f, 0.f, 0.f);
            int gr = rowBase + a_row[i];
            if (gr < M && k0 + a_kc[i] < K)
                av[i] = *(const float4*)(A + (size_t)gr * K + k0 + a_kc[i]);
        }
        int kc = k0 >> 4;
        const uint4* sp = (const uint4*)((b_sel ? btlo : bthi) + (size_t)kc * BTILE_WORDS);
        bv = sp[b_idx];
    };

    auto sts_tile = [&](int s) {
#pragma unroll
        for (int i = 0; i < 2; i++) {
            float* b = &As[s][a_soff[i]];
            *(float2*)b = make_float2(av[i].x, av[i].y);
            *(float2*)(b + 4) = make_float2(av[i].z, av[i].w);
        }
        uint4* dp = (uint4*)(b_sel ? Bl[s] : Bh[s]);
        dp[b_idx] = bv;
    };

    ldg_tile(0);
    sts_tile(0);
    __syncthreads();
    int stage = 0;

    for (int k0 = 0; k0 < K; k0 += 16) {
        bool has_next = (k0 + 16) < K;
        if (has_next) ldg_tile(k0 + 16);

        uint32_t ah[2][4], al[2][4];
#pragma unroll
        for (int mt = 0; mt < 2; mt++) {
            const float* ap = &As[stage][(wm * 2 + mt) * 256 + lane * 4];
            float4 x = *(const float4*)ap;
            float4 y = *(const float4*)(ap + 128);
            float f[8] = {x.x, x.y, x.z, x.w, y.x, y.y, y.z, y.w};
#pragma unroll
            for (int r = 0; r < 4; r++) {
                __half2 hh = __floats2half2_rn(f[2 * r], f[2 * r + 1]);
                ah[mt][r] = *reinterpret_cast<uint32_t*>(&hh);
                float2 bk = __half22float2(hh);
                __half2 ll = __floats2half2_rn(f[2 * r] - bk.x, f[2 * r + 1] - bk.y);
                al[mt][r] = *reinterpret_cast<uint32_t*>(&ll);
            }
        }
        uint32_t bh[4][2], bl[4][2];
#pragma unroll
        for (int nt = 0; nt < 4; nt++) {
            uint2 v = *(const uint2*)(&Bh[stage][(wn * 4 + nt) * 64 + lane * 2]);
            bh[nt][0] = v.x; bh[nt][1] = v.y;
            uint2 w2 = *(const uint2*)(&Bl[stage][(wn * 4 + nt) * 64 + lane * 2]);
            bl[nt][0] = w2.x; bl[nt][1] = w2.y;
        }
#define MMA(CC, AA, BB) \
    asm volatile("mma.sync.aligned.m16n8k16.row.col.f32.f16.f16.f32 " \
                 "{%0,%1,%2,%3}, {%4,%5,%6,%7}, {%8,%9}, {%0,%1,%2,%3};" \
                 : "+f"(CC[0]), "+f"(CC[1]), "+f"(CC[2]), "+f"(CC[3]) \
                 : "r"(AA[0]), "r"(AA[1]), "r"(AA[2]), "r"(AA[3]), "r"(BB[0]), "r"(BB[1]))
#define MMALO(CC, AA, BB) \
    asm volatile("mma.sync.aligned.m16n8k16.row.col.f16.f16.f16.f16 " \
                 "{%0,%1}, {%2,%3,%4,%5}, {%6,%7}, {%0,%1};" \
                 : "+r"(CC[0]), "+r"(CC[1]) \
                 : "r"(AA[0]), "r"(AA[1]), "r"(AA[2]), "r"(AA[3]), "r"(BB[0]), "r"(BB[1]))
#pragma unroll
        for (int mt = 0; mt < 2; mt++)
#pragma unroll
            for (int nt = 0; nt < 4; nt++) MMA(acc[mt][nt], ah[mt], bh[nt]);
#pragma unroll
        for (int mt = 0; mt < 2; mt++)
#pragma unroll
            for (int nt = 0; nt < 4; nt++) MMALO(accl[mt][nt], al[mt], bh[nt]);
#pragma unroll
        for (int mt = 0; mt < 2; mt++)
#pragma unroll
            for (int nt = 0; nt < 4; nt++) MMALO(accl[mt][nt], ah[mt], bl[nt]);
#undef MMA
#undef MMALO

        if (has_next) {
            sts_tile(stage ^ 1);
            __syncthreads();
            stage ^= 1;
        }
    }

    // ---- merge f16 lo accumulators into f32 ----
#pragma unroll
    for (int mt = 0; mt < 2; mt++)
#pragma unroll
        for (int nt = 0; nt < 4; nt++) {
            __half2 l0 = *reinterpret_cast<__half2*>(&accl[mt][nt][0]);
            __half2 l1 = *reinterpret_cast<__half2*>(&accl[mt][nt][1]);
            float2 f0 = __half22float2(l0);
            float2 f1 = __half22float2(l1);
            acc[mt][nt][0] += f0.x;
            acc[mt][nt][1] += f0.y;
            acc[mt][nt][2] += f1.x;
            acc[mt][nt][3] += f1.y;
        }

    // ---- epilogue ----
#pragma unroll
    for (int nt = 0; nt < 4; nt++) {
        int col = colBase + wn * 32 + nt * 8 + qq * 2;
        if (col >= Nc) continue;
        float bia0 = bias[col], bia1 = bias[col + 1];
        float sc0 = 1.f, sc1 = 1.f, sh0 = 0.f, sh1 = 0.f;
        if (MODE >= 2) {
            sc0 = bng[col] * rsqrtf(bnv[col] + BN_EPS);
            sc1 = bng[col + 1] * rsqrtf(bnv[col + 1] + BN_EPS);
            sh0 = bnb[col] - bnm[col] * sc0;
            sh1 = bnb[col + 1] - bnm[col + 1] * sc1;
        }
#pragma unroll
        for (int mt = 0; mt < 2; mt++) {
            float* c = acc[mt][nt];
#pragma unroll
            for (int half = 0; half < 2; half++) {
                int r = rowBase + wm * 32 + mt * 16 + gg + half * 8;
                if (r >= M) continue;
                float v0 = c[half * 2 + 0] + bia0;
                float v1 = c[half * 2 + 1] + bia1;
                if (MODE >= 2) { v0 = v0 * sc0 + sh0; v1 = v1 * sc1 + sh1; }
                if (MODE == 1 || MODE == 3) { v0 = fmaxf(v0, 0.f); v1 = fmaxf(v1, 0.f); }
                *(float2*)(C + (size_t)r * Nc + col) = make_float2(v0, v1);
            }
        }
    }
}

// ---------------- avg pool per graph ----------------
__device__ __forceinline__ int lower_bound_dev(const int* a, int n, int v) {
    int lo = 0, hi = n;
    while (lo < hi) {
        int m = (lo + hi) >> 1;
        if (a[m] < v) lo = m + 1; else hi = m;
    }
    return lo;
}

__global__ void pool_kernel(const float* __restrict__ h, const int* __restrict__ gid,
                            float* __restrict__ gavg, int N) {
    __shared__ int sh[2];
    int g = blockIdx.x;
    if (threadIdx.x == 0) sh[0] = lower_bound_dev(gid, N, g);
    if (threadIdx.x == 1) sh[1] = lower_bound_dev(gid, N, g + 1);
    __syncthreads();
    int lo = sh[0], hi = sh[1];
    int d = threadIdx.x;
    if (d >= D) return;
    float s = 0.f;
    for (int n = lo; n < hi; n++) s += h[(size_t)n * D + d];
    float cnt = (float)(hi - lo);
    gavg[(size_t)g * D + d] = s / fmaxf(cnt, 1.0f);
}

// ---------------- small fp32 GEMM for the head ----------------
__global__ __launch_bounds__(256)
void head_gemm_kernel(const float* __restrict__ A, const float* __restrict__ B,
                      const float* __restrict__ bias, float* __restrict__ C,
                      int M, int K, int Nc) {
    int row = blockIdx.y * 16 + (threadIdx.x >> 4);
    int col = blockIdx.x * 64 + (threadIdx.x & 15) * 4;
    if (row >= M || col >= Nc) return;
    float s0 = 0.f, s1 = 0.f, s2 = 0.f, s3 = 0.f;
    const float* a = A + (size_t)row * K;
    for (int k = 0; k < K; k++) {
        float av = a[k];
        const float* b = B + (size_t)k * Nc + col;
        s0 += av * b[0]; s1 += av * b[1]; s2 += av * b[2]; s3 += av * b[3];
    }
    float* out = C + (size_t)row * Nc + col;
    out[0] = s0 + bias[col];
    out[1] = s1 + bias[col + 1];
    out[2] = s2 + bias[col + 2];
    out[3] = s3 + bias[col + 3];
}

// ---------------- launch ----------------
extern "C" void kernel_launch(void* const* d_in, const int* in_sizes, int n_in,
                              void* d_out, int out_size) {
    const int* an  = (const int*)d_in[0];
    const int* ct  = (const int*)d_in[1];
    const int* bt  = (const int*)d_in[2];
    const int* bdt = (const int*)d_in[3];
    const int* src = (const int*)d_in[4];
    const int* dst = (const int*)d_in[5];
    const int* gid = (const int*)d_in[6];
    const int N = in_sizes[0];
    const int E = in_sizes[2];

    int p = 7;
    if (n_in > 7 && in_sizes[7] == 1) p = 8;
    const float* node_emb0 = (const float*)d_in[p + 0];
    const float* node_emb1 = (const float*)d_in[p + 1];
    const float* edge_emb0 = (const float*)d_in[p + 2];
    const float* edge_emb1 = (const float*)d_in[p + 3];
    const float* W1  = (const float*)d_in[p + 4];
    const float* b1  = (const float*)d_in[p + 5];
    const float* W2  = (const float*)d_in[p + 6];
    const float* b2  = (const float*)d_in[p + 7];
    const float* bng = (const float*)d_in[p + 8];
    const float* bnb = (const float*)d_in[p + 9];
    const float* bnm = (const float*)d_in[p + 10];
    const float* bnv = (const float*)d_in[p + 11];
    const float* Wd  = (const float*)d_in[p + 12];
    const float* bd  = (const float*)d_in[p + 13];
    const int G = out_size / 256;

    float *h, *agg, *t, *cnt, *gavg;
    int *deg, *offs, *bsum, *cursor, *ssrc;
    uint32_t *w1hi, *w1lo, *w2hi, *w2lo;
    cudaGetSymbolAddress((void**)&h, g_h);
    cudaGetSymbolAddress((void**)&agg, g_agg);
    cudaGetSymbolAddress((void**)&t, g_t);
    cudaGetSymbolAddress((void**)&cnt, g_cnt);
    cudaGetSymbolAddress((void**)&gavg, g_gavg);
    cudaGetSymbolAddress((void**)&deg, g_deg);
    cudaGetSymbolAddress((void**)&offs, g_offs);
    cudaGetSymbolAddress((void**)&bsum, g_bsum);
    cudaGetSymbolAddress((void**)&cursor, g_cursor);
    cudaGetSymbolAddress((void**)&ssrc, g_ssrc);
    cudaGetSymbolAddress((void**)&w1hi, g_w1hi);
    cudaGetSymbolAddress((void**)&w1lo, g_w1lo);
    cudaGetSymbolAddress((void**)&w2hi, g_w2hi);
    cudaGetSymbolAddress((void**)&w2lo, g_w2lo);

    const int ND = N * D;
    const int words1 = NT1 * NKC1 * BTILE_WORDS;
    const int words2 = NT2 * NKC2 * BTILE_WORDS;
    const int mtiles = (N + 127) / 128;
    const int nscan = N + 1;                  // scan deg[0..N] (deg[N]=0 -> offs[N]=E)
    const int nb = (nscan + 1023) / 1024;     // <= 256 for N <= 262143

    init_h_zero_kernel<<<(ND + 255) / 256, 256>>>(an, ct, node_emb0, node_emb1, h, cnt, deg, N);
    count_kernel<<<(E + 255) / 256, 256>>>(bt, bdt, dst, cnt, deg, E);
    // CSR build
    scan_block_kernel<<<nb, 1024>>>(deg, offs, bsum, nscan);
    scan_sums_kernel<<<1, 256>>>(bsum, nb);
    scan_add_kernel<<<nb, 1024>>>(offs, bsum, cursor, nscan, N);
    fill_kernel<<<(E + 255) / 256, 256>>>(src, dst, cursor, ssrc, E);

    for (int l = 0; l < NLAYERS; l++) {
        prep_w_kernel<<<(words1 + 255) / 256, 256>>>(
            W1 + (size_t)l * D * TWO_D,
            w1hi + (size_t)l * words1, w1lo + (size_t)l * words1,
            D, TWO_D, NKC1, words1);
        gather_agg_kernel<<<(N * 75 + 255) / 256, 256>>>(
            h, offs, ssrc, cnt,
            edge_emb0 + (size_t)l * 6 * D, edge_emb1 + (size_t)l * 3 * D, agg, N);
        gemm_f16_kernel<1><<<dim3(NT1, mtiles), 256>>>(
            agg, w1hi + (size_t)l * words1, w1lo + (size_t)l * words1,
            b1 + (size_t)l * TWO_D, nullptr, nullptr, nullptr, nullptr,
            t, N, D, TWO_D, NKC1);
        prep_w_kernel<<<(words2 + 255) / 256, 256>>>(
            W2 + (size_t)l * TWO_D * D,
            w2hi + (size_t)l * words2, w2lo + (size_t)l * words2,
            TWO_D, D, NKC2, words2);
        if (l < NLAYERS - 1) {
            gemm_f16_kernel<3><<<dim3(NT2, mtiles), 256>>>(
                t, w2hi + (size_t)l * words2, w2lo + (size_t)l * words2,
                b2 + (size_t)l * D, bng + (size_t)l * D, bnb + (size_t)l * D,
                bnm + (size_t)l * D, bnv + (size_t)l * D,
                h, N, TWO_D, D, NKC2);
        } else {
            gemm_f16_kernel<2><<<dim3(NT2, mtiles), 256>>>(
                t, w2hi + (size_t)l * words2, w2lo + (size_t)l * words2,
                b2 + (size_t)l * D, bng + (size_t)l * D, bnb + (size_t)l * D,
                bnm + (size_t)l * D, bnv + (size_t)l * D,
                h, N, TWO_D, D, NKC2);
        }
    }

    pool_kernel<<<G, 320>>>(h, gid, gavg, N);
    head_gemm_kernel<<<dim3(256 / 64, (G + 15) / 16), 256>>>(gavg, Wd, bd, (float*)d_out, G, D, 256);
}